// round 6
// baseline (speedup 1.0000x reference)
#include <cuda_runtime.h>
#include <cuda_bf16.h>

// MeanSquaredError2: loss = [ sum(h^2) + sum_{vis}(1 - 2*h[b,j,xi,yi]) ] * 2/size
// o input unused. Single-kernel HBM-bound streaming reduction.
// Proven-best streaming shape: plain grid-stride, one LDG.128/iter (all
// explicit unrolls regressed via cross-CTA L1tex queue contention).
// This round: scattered one-hot correction issued BEFORE the streaming loop
// (its DRAM latency hides under the stream instead of serializing at the
// end), bulk loads back to default __ldg policy (marginally better than
// __ldcs in R1 vs R5 evidence), fused last-block finalize retained.

#define COLS 14
#define CELLS (COLS * COLS)   // 196
#define THREADS 256

__device__ float         g_partial = 0.0f;
__device__ unsigned int  g_arrived = 0u;

__global__ __launch_bounds__(THREADS) void mse_reduce_kernel(
    const float4* __restrict__ h4, long long n4,
    const float*  __restrict__ h,
    const float*  __restrict__ t,
    const int*    __restrict__ v,
    int npairs, float scale, float* __restrict__ out)
{
    const int tid  = threadIdx.x;
    const long long gid = (long long)blockIdx.x * THREADS + tid;
    const long long gstride = (long long)gridDim.x * THREADS;

    float local = 0.0f;

    // One-hot correction FIRST: scattered loads issue before the stream and
    // complete under its latency shadow. One (b,j) pair per global thread.
    if (gid < npairs) {
        int p = (int)gid;
        if (__ldg(&v[p]) == 1) {
            float tx = __ldg(&t[2 * p]);
            float ty = __ldg(&t[2 * p + 1]);
            int xi = (int)(tx * (float)COLS);
            int yi = (int)(ty * (float)COLS);
            xi = min(max(xi, 0), COLS - 1);
            yi = min(max(yi, 0), COLS - 1);
            float hv = __ldg(&h[(long long)p * CELLS + xi * COLS + yi]);
            local += 1.0f - 2.0f * hv;
        }
    }

    // Main streaming pass: one coalesced LDG.128 per iteration.
    for (long long i = gid; i < n4; i += gstride) {
        float4 x = __ldg(&h4[i]);
        local += x.x * x.x + x.y * x.y + x.z * x.z + x.w * x.w;
    }

    // Warp reduce
    #pragma unroll
    for (int off = 16; off > 0; off >>= 1)
        local += __shfl_xor_sync(0xFFFFFFFFu, local, off);

    // Block reduce via shared
    __shared__ float warp_sums[THREADS / 32];
    int lane = tid & 31, wid = tid >> 5;
    if (lane == 0) warp_sums[wid] = local;
    __syncthreads();
    if (wid == 0) {
        local = (lane < (THREADS >> 5)) ? warp_sums[lane] : 0.0f;
        #pragma unroll
        for (int off = 4; off > 0; off >>= 1)
            local += __shfl_xor_sync(0xFFFFFFFFu, local, off);
        if (lane == 0) {
            atomicAdd(&g_partial, local);
            __threadfence();
            unsigned int prev = atomicAdd(&g_arrived, 1u);
            if (prev == gridDim.x - 1) {
                // Last block: publish result, reset scratch for next replay.
                float total = atomicAdd(&g_partial, 0.0f);  // ordered read
                out[0] = total * scale;
                g_partial = 0.0f;
                __threadfence();
                g_arrived = 0u;
            }
        }
    }
}

extern "C" void kernel_launch(void* const* d_in, const int* in_sizes, int n_in,
                              void* d_out, int out_size)
{
    // Inputs (metadata order): o (unused), h, t, v
    const float* h = (const float*)d_in[1];
    const float* t = (const float*)d_in[2];
    const int*   v = (const int*)d_in[3];
    float* out = (float*)d_out;

    long long hsize = (long long)in_sizes[1];       // B*NJ*14*14
    long long n4 = hsize / 4;                       // divisible
    int npairs = in_sizes[3];                       // B*NJ
    float scale = 2.0f / (float)hsize;              // 1 / (size/2)

    int blocks = 1184;                              // 148 SMs * 8 blocks, one wave
    long long total = (long long)blocks * THREADS;
    if (total < npairs) blocks = (npairs + THREADS - 1) / THREADS;

    mse_reduce_kernel<<<blocks, THREADS>>>(
        (const float4*)h, n4, h, t, v, npairs, scale, out);
}

// round 7
// speedup vs baseline: 1.0029x; 1.0029x over previous
#include <cuda_runtime.h>
#include <cuda_bf16.h>

// MeanSquaredError2: loss = [ sum(h^2) + sum_{vis}(1 - 2*h[b,j,xi,yi]) ] * 2/size
// o input unused. Single-kernel HBM-bound streaming reduction.
// Converged configuration from 6 rounds of evidence:
//  - plain grid-stride, one LDG.128/iter (all explicit unrolls regressed:
//    cross-CTA L1tex queue contention at MLP_p1>=2)
//  - default __ldg cache policy (__ldcs cost ~0.6us: R1 vs R5)
//  - scattered one-hot correction AFTER the stream (before-stream delayed
//    stream ramp-up, cost 1.8us: R6)
//  - fused last-block finalize (removes init-kernel launch, ~1.6us: R5)

#define COLS 14
#define CELLS (COLS * COLS)   // 196
#define THREADS 256

__device__ float         g_partial = 0.0f;
__device__ unsigned int  g_arrived = 0u;

__global__ __launch_bounds__(THREADS) void mse_reduce_kernel(
    const float4* __restrict__ h4, long long n4,
    const float*  __restrict__ h,
    const float*  __restrict__ t,
    const int*    __restrict__ v,
    int npairs, float scale, float* __restrict__ out)
{
    const int tid  = threadIdx.x;
    const long long gid = (long long)blockIdx.x * THREADS + tid;
    const long long gstride = (long long)gridDim.x * THREADS;

    float local = 0.0f;

    // Main streaming pass: one coalesced LDG.128 per iteration.
    for (long long i = gid; i < n4; i += gstride) {
        float4 x = __ldg(&h4[i]);
        local += x.x * x.x + x.y * x.y + x.z * x.z + x.w * x.w;
    }

    // One-hot correction: one (b,j) pair per global thread; its dependent
    // scattered loads overlap with other warps still streaming.
    if (gid < npairs) {
        int p = (int)gid;
        if (__ldg(&v[p]) == 1) {
            float tx = __ldg(&t[2 * p]);
            float ty = __ldg(&t[2 * p + 1]);
            int xi = (int)(tx * (float)COLS);
            int yi = (int)(ty * (float)COLS);
            xi = min(max(xi, 0), COLS - 1);
            yi = min(max(yi, 0), COLS - 1);
            float hv = __ldg(&h[(long long)p * CELLS + xi * COLS + yi]);
            local += 1.0f - 2.0f * hv;
        }
    }

    // Warp reduce
    #pragma unroll
    for (int off = 16; off > 0; off >>= 1)
        local += __shfl_xor_sync(0xFFFFFFFFu, local, off);

    // Block reduce via shared
    __shared__ float warp_sums[THREADS / 32];
    int lane = tid & 31, wid = tid >> 5;
    if (lane == 0) warp_sums[wid] = local;
    __syncthreads();
    if (wid == 0) {
        local = (lane < (THREADS >> 5)) ? warp_sums[lane] : 0.0f;
        #pragma unroll
        for (int off = 4; off > 0; off >>= 1)
            local += __shfl_xor_sync(0xFFFFFFFFu, local, off);
        if (lane == 0) {
            atomicAdd(&g_partial, local);
            __threadfence();
            unsigned int prev = atomicAdd(&g_arrived, 1u);
            if (prev == gridDim.x - 1) {
                // Last block: publish result, reset scratch for next replay.
                float total = atomicAdd(&g_partial, 0.0f);  // ordered read
                out[0] = total * scale;
                g_partial = 0.0f;
                __threadfence();
                g_arrived = 0u;
            }
        }
    }
}

extern "C" void kernel_launch(void* const* d_in, const int* in_sizes, int n_in,
                              void* d_out, int out_size)
{
    // Inputs (metadata order): o (unused), h, t, v
    const float* h = (const float*)d_in[1];
    const float* t = (const float*)d_in[2];
    const int*   v = (const int*)d_in[3];
    float* out = (float*)d_out;

    long long hsize = (long long)in_sizes[1];       // B*NJ*14*14
    long long n4 = hsize / 4;                       // divisible
    int npairs = in_sizes[3];                       // B*NJ
    float scale = 2.0f / (float)hsize;              // 1 / (size/2)

    int blocks = 1184;                              // 148 SMs * 8 blocks, one wave
    long long total = (long long)blocks * THREADS;
    if (total < npairs) blocks = (npairs + THREADS - 1) / THREADS;

    mse_reduce_kernel<<<blocks, THREADS>>>(
        (const float4*)h, n4, h, t, v, npairs, scale, out);
}

// round 8
// speedup vs baseline: 1.0667x; 1.0636x over previous
#include <cuda_runtime.h>
#include <cuda_bf16.h>

// MeanSquaredError2: loss = [ sum(h^2) + sum_{vis}(1 - 2*h[b,j,xi,yi]) ] * 2/size
// o input unused. Single-kernel HBM-bound streaming reduction.
// CONVERGED CONFIG (= R5, measured best 31.5us total; R7's ldg probe and
// R6's correction-first probe both regressed; unrolls all regressed):
//  - plain grid-stride, one LDG.128 (__ldcs, read-once evict-first) per iter
//  - scattered one-hot correction AFTER the stream
//  - fused last-block finalize (no separate init kernel)

#define COLS 14
#define CELLS (COLS * COLS)   // 196
#define THREADS 256

__device__ float         g_partial = 0.0f;
__device__ unsigned int  g_arrived = 0u;

__global__ __launch_bounds__(THREADS) void mse_reduce_kernel(
    const float4* __restrict__ h4, long long n4,
    const float*  __restrict__ h,
    const float*  __restrict__ t,
    const int*    __restrict__ v,
    int npairs, float scale, float* __restrict__ out)
{
    const int tid  = threadIdx.x;
    const long long gid = (long long)blockIdx.x * THREADS + tid;
    const long long gstride = (long long)gridDim.x * THREADS;

    float local = 0.0f;

    // Main streaming pass: one coalesced LDG.128 per iteration (evict-first).
    for (long long i = gid; i < n4; i += gstride) {
        float4 x = __ldcs(&h4[i]);
        local += x.x * x.x + x.y * x.y + x.z * x.z + x.w * x.w;
    }

    // One-hot correction: one (b,j) pair per global thread.
    if (gid < npairs) {
        int p = (int)gid;
        if (__ldg(&v[p]) == 1) {
            float tx = __ldg(&t[2 * p]);
            float ty = __ldg(&t[2 * p + 1]);
            int xi = (int)(tx * (float)COLS);
            int yi = (int)(ty * (float)COLS);
            xi = min(max(xi, 0), COLS - 1);
            yi = min(max(yi, 0), COLS - 1);
            float hv = __ldg(&h[(long long)p * CELLS + xi * COLS + yi]);
            local += 1.0f - 2.0f * hv;
        }
    }

    // Warp reduce
    #pragma unroll
    for (int off = 16; off > 0; off >>= 1)
        local += __shfl_xor_sync(0xFFFFFFFFu, local, off);

    // Block reduce via shared
    __shared__ float warp_sums[THREADS / 32];
    int lane = tid & 31, wid = tid >> 5;
    if (lane == 0) warp_sums[wid] = local;
    __syncthreads();
    if (wid == 0) {
        local = (lane < (THREADS >> 5)) ? warp_sums[lane] : 0.0f;
        #pragma unroll
        for (int off = 4; off > 0; off >>= 1)
            local += __shfl_xor_sync(0xFFFFFFFFu, local, off);
        if (lane == 0) {
            atomicAdd(&g_partial, local);
            __threadfence();
            unsigned int prev = atomicAdd(&g_arrived, 1u);
            if (prev == gridDim.x - 1) {
                // Last block: publish result, reset scratch for next replay.
                float total = atomicAdd(&g_partial, 0.0f);  // ordered read
                out[0] = total * scale;
                g_partial = 0.0f;
                __threadfence();
                g_arrived = 0u;
            }
        }
    }
}

extern "C" void kernel_launch(void* const* d_in, const int* in_sizes, int n_in,
                              void* d_out, int out_size)
{
    // Inputs (metadata order): o (unused), h, t, v
    const float* h = (const float*)d_in[1];
    const float* t = (const float*)d_in[2];
    const int*   v = (const int*)d_in[3];
    float* out = (float*)d_out;

    long long hsize = (long long)in_sizes[1];       // B*NJ*14*14
    long long n4 = hsize / 4;                       // divisible
    int npairs = in_sizes[3];                       // B*NJ
    float scale = 2.0f / (float)hsize;              // 1 / (size/2)

    int blocks = 1184;                              // 148 SMs * 8 blocks
    long long total = (long long)blocks * THREADS;
    if (total < npairs) blocks = (npairs + THREADS - 1) / THREADS;

    mse_reduce_kernel<<<blocks, THREADS>>>(
        (const float4*)h, n4, h, t, v, npairs, scale, out);
}